// round 12
// baseline (speedup 1.0000x reference)
#include <cuda_runtime.h>
#include <cub/cub.cuh>
#include <thrust/iterator/counting_iterator.h>
#include <thrust/iterator/transform_iterator.h>
#include <stdint.h>

#define NMAX 1000000
#define EMAX 8000000

// node-phase sort buffers (voxel key u32, node id u32)
__device__ unsigned g_vk[NMAX], g_vk2[NMAX];
__device__ unsigned g_vv[NMAX], g_vv2[NMAX];
__device__ int g_inv[NMAX];                    // node -> coarse rank
__device__ unsigned g_seg[NMAX];               // rank -> segment start in sorted order
__device__ unsigned g_pref[NMAX];              // node head-flag inclusive scan
// edge bucket machinery (bucket = source coarse rank s)
__device__ unsigned g_cnt[NMAX + 1];           // per-bucket edge counts
__device__ unsigned g_off[NMAX + 1];           // exclusive scan of counts
__device__ unsigned g_cur[NMAX];               // scatter cursors
__device__ unsigned g_ucnt[NMAX + 1];          // per-bucket unique counts
__device__ unsigned g_uoff[NMAX + 1];          // exclusive scan; g_uoff[n] = M
__device__ unsigned g_dbuf[EMAX];              // bucketed d values
__device__ unsigned g_U;                       // number of unique voxels
// 64 MB CUB temp — VALIDATED: 8 MB crashed the container; 64 MB runs clean.
__device__ __align__(256) unsigned char g_temp[64u << 20];

__global__ void k_vox(const float* __restrict__ pos, const int* __restrict__ batch, int n) {
    int i = blockIdx.x * blockDim.x + threadIdx.x;
    if (i >= n) return;
    float px = pos[3 * i + 0];
    float py = pos[3 * i + 1];
    float pt = pos[3 * i + 2];
    // VALIDATED (R9): match XLA's pos / POOL lowering = multiply by rounded
    // reciprocal, single RN multiply. IEEE division does NOT match.
    int qx = (int)floorf(__fmul_rn(px, 0.25f));
    int qy = (int)floorf(__fmul_rn(py, 0.25f));
    int qt = (int)floorf(__fmul_rn(pt, 0.00025f));
    int b = batch[i];
    g_vk[i] = (unsigned)(((b * 128 + qx) * 128 + qy) * 64 + qt);  // < 2^24
    g_vv[i] = (unsigned)i;
}

struct NodeHeadOp {
    const unsigned* sk;
    __host__ __device__ __forceinline__ unsigned operator()(int p) const {
        return (p == 0) || (sk[p] != sk[p - 1]);
    }
};

// head p: rank r = g_pref[p]-1; non-head p: pad slot = U + (p - g_pref[p])
__global__ void k_nodeinfo(const unsigned* __restrict__ sk, const unsigned* __restrict__ sv,
                           float* __restrict__ out_q, float* __restrict__ out_b,
                           float* __restrict__ out_e, int E, int n) {
    int p = blockIdx.x * blockDim.x + threadIdx.x;
    if (p >= n) return;
    int U = (int)g_pref[n - 1];
    if (p == n - 1) g_U = (unsigned)U;
    unsigned k = sk[p];
    int pr = (int)g_pref[p];
    g_inv[sv[p]] = pr - 1;
    bool head = (p == 0) || (sk[p - 1] != k);
    if (head) {
        int r = pr - 1;
        g_seg[r] = (unsigned)p;
        out_q[3 * r + 0] = (float)((k >> 13) & 127);  // qx
        out_q[3 * r + 1] = (float)((k >> 6) & 127);   // qy
        out_q[3 * r + 2] = (float)(k & 63);           // qt
        out_b[r] = (float)(k >> 20);                  // batch
        ((float2*)out_e)[E + r] = make_float2((float)r, (float)r);  // self loop
    } else {
        int pad = U + (p - pr);
        out_q[3 * pad + 0] = -1.0f;
        out_q[3 * pad + 1] = -1.0f;
        out_q[3 * pad + 2] = -1.0f;
        out_b[pad] = -1.0f;
        ((float2*)out_e)[E + pad] = make_float2(-1.0f, -1.0f);
    }
}

// grid-stride segmented max (single wave)
__global__ void k_segmax(const float* __restrict__ x, const unsigned* __restrict__ sv,
                         float* __restrict__ out, int n, int F) {
    int U = (int)g_U;
    int rpb = blockDim.x / F;
    int f = threadIdx.x % F;
    int r0 = blockIdx.x * rpb + threadIdx.x / F;
    int rstride = gridDim.x * rpb;
    for (int r = r0; r < n; r += rstride) {
        if (r >= U) { out[(long long)r * F + f] = 0.0f; continue; }
        int start = (int)g_seg[r];
        int end = (r + 1 < U) ? (int)g_seg[r + 1] : n;
        float m = -__int_as_float(0x7f800000);
        for (int p = start; p < end; p++)
            m = fmaxf(m, x[(long long)sv[p] * F + f]);
        out[(long long)r * F + f] = m;
    }
}

// ---- edge path: bucket counting sort by s, tiny per-bucket d-sorts ----

__global__ void k_hist(const int2* __restrict__ eidx, int E) {
    int stride = gridDim.x * blockDim.x;
    for (int e = blockIdx.x * blockDim.x + threadIdx.x; e < E; e += stride) {
        int2 sd = eidx[e];
        int s = g_inv[sd.x];
        int d = g_inv[sd.y];
        if (s != d) atomicAdd(&g_cnt[s], 1u);   // self loops dropped entirely
    }
}

__global__ void k_bscatter(const int2* __restrict__ eidx, int E) {
    int stride = gridDim.x * blockDim.x;
    for (int e = blockIdx.x * blockDim.x + threadIdx.x; e < E; e += stride) {
        int2 sd = eidx[e];
        int s = g_inv[sd.x];
        int d = g_inv[sd.y];
        if (s == d) continue;
        unsigned p = g_off[s] + atomicAdd(&g_cur[s], 1u);
        g_dbuf[p] = (unsigned)d;
    }
}

#define BCAP 32
// one thread per bucket: insertion-sort d's (smem, gmem fallback), count unique
__global__ void k_bsort(int n) {
    __shared__ unsigned sm[256 * BCAP];
    unsigned* loc = sm + threadIdx.x * BCAP;
    int stride = gridDim.x * blockDim.x;
    for (int b = blockIdx.x * blockDim.x + threadIdx.x; b < n; b += stride) {
        if (b == 0) g_ucnt[n] = 0;
        int st = (int)g_off[b];
        int k = (int)g_off[b + 1] - st;
        if (k == 0) { g_ucnt[b] = 0; continue; }
        unsigned u;
        if (k <= BCAP) {
            for (int i = 0; i < k; i++) {
                unsigned v = g_dbuf[st + i];
                int j = i;
                while (j > 0 && loc[j - 1] > v) { loc[j] = loc[j - 1]; j--; }
                loc[j] = v;
            }
            u = 1;
            for (int i = 1; i < k; i++) u += (loc[i] != loc[i - 1]);
            for (int i = 0; i < k; i++) g_dbuf[st + i] = loc[i];
        } else {
            // rare fallback: in-place gmem insertion sort
            for (int i = 1; i < k; i++) {
                unsigned v = g_dbuf[st + i];
                int j = i;
                while (j > 0 && g_dbuf[st + j - 1] > v) { g_dbuf[st + j] = g_dbuf[st + j - 1]; j--; }
                g_dbuf[st + j] = v;
            }
            u = 1;
            for (int i = 1; i < k; i++) u += (g_dbuf[st + i] != g_dbuf[st + i - 1]);
        }
        g_ucnt[b] = u;
    }
}

// one thread per bucket: emit unique (s=b, d) at uoff[b]
__global__ void k_bemit(float2* __restrict__ out_e, int n) {
    int stride = gridDim.x * blockDim.x;
    for (int b = blockIdx.x * blockDim.x + threadIdx.x; b < n; b += stride) {
        int st = (int)g_off[b];
        int k = (int)g_off[b + 1] - st;
        if (k == 0) continue;
        int base = (int)g_uoff[b];
        float fb = (float)b;
        unsigned prev = 0xFFFFFFFFu;
        int j = 0;
        for (int i = 0; i < k; i++) {
            unsigned d = g_dbuf[st + i];
            if (i == 0 || d != prev) {
                out_e[base + j] = make_float2(fb, (float)d);
                j++;
            }
            prev = d;
        }
    }
}

__global__ void k_pad(float2* __restrict__ out_e, int E, int n) {
    int M = (int)g_uoff[n];
    int stride = gridDim.x * blockDim.x;
    for (int e = M + blockIdx.x * blockDim.x + threadIdx.x; e < E; e += stride)
        out_e[e] = make_float2(-1.0f, -1.0f);
}

extern "C" void kernel_launch(void* const* d_in, const int* in_sizes, int n_in,
                              void* d_out, int out_size) {
    const float* x = (const float*)d_in[0];
    const float* pos = (const float*)d_in[1];
    const int* eidx = (const int*)d_in[2];
    const int* batch = (const int*)d_in[3];

    int n = in_sizes[1] / 3;          // nodes
    int F = in_sizes[0] / n;          // feature dim (64)
    int E = in_sizes[2] / 2;          // edges
    float* out = (float*)d_out;

    long long OFF_Q = (long long)n * F;             // uniq_qpos
    long long OFF_E = OFF_Q + 3LL * n;              // ei_out
    long long OFF_B = OFF_E + 2LL * (E + n);        // new_batch

    void *p_vk, *p_vk2, *p_vv, *p_vv2, *p_pref, *p_cnt, *p_off, *p_cur, *p_ucnt, *p_uoff, *p_temp;
    cudaGetSymbolAddress(&p_vk, g_vk);
    cudaGetSymbolAddress(&p_vk2, g_vk2);
    cudaGetSymbolAddress(&p_vv, g_vv);
    cudaGetSymbolAddress(&p_vv2, g_vv2);
    cudaGetSymbolAddress(&p_pref, g_pref);
    cudaGetSymbolAddress(&p_cnt, g_cnt);
    cudaGetSymbolAddress(&p_off, g_off);
    cudaGetSymbolAddress(&p_cur, g_cur);
    cudaGetSymbolAddress(&p_ucnt, g_ucnt);
    cudaGetSymbolAddress(&p_uoff, g_uoff);
    cudaGetSymbolAddress(&p_temp, g_temp);

    cudaStream_t s = 0;
    const int T = 256;
    const int GS = 2048;   // grid-stride grid size (single wave)

    // --- init bucket counters ---
    cudaMemsetAsync(p_cnt, 0, (size_t)(n + 1) * 4, s);
    cudaMemsetAsync(p_cur, 0, (size_t)n * 4, s);

    // --- node path: sort 1M (vox,node) pairs on 24-bit key ---
    k_vox<<<(n + T - 1) / T, T, 0, s>>>(pos, batch, n);
    const unsigned *sortedK, *sortedV;
    {
        cub::DoubleBuffer<unsigned> dk((unsigned*)p_vk, (unsigned*)p_vk2);
        cub::DoubleBuffer<unsigned> dv((unsigned*)p_vv, (unsigned*)p_vv2);
        size_t tb = 0;
        cub::DeviceRadixSort::SortPairs(nullptr, tb, dk, dv, n, 0, 24, s);
        cub::DeviceRadixSort::SortPairs(p_temp, tb, dk, dv, n, 0, 24, s);
        sortedK = dk.Current();
        sortedV = dv.Current();
    }
    {
        NodeHeadOp op{sortedK};
        auto it = thrust::make_transform_iterator(thrust::make_counting_iterator(0), op);
        size_t tb = 0;
        cub::DeviceScan::InclusiveSum(nullptr, tb, it, (unsigned*)p_pref, n, s);
        cub::DeviceScan::InclusiveSum(p_temp, tb, it, (unsigned*)p_pref, n, s);
    }
    k_nodeinfo<<<(n + T - 1) / T, T, 0, s>>>(sortedK, sortedV,
                                             out + OFF_Q, out + OFF_B, out + OFF_E, E, n);

    // --- pooled features ---
    k_segmax<<<GS, T, 0, s>>>(x, sortedV, out, n, F);

    // --- edge path: bucket counting sort by s ---
    k_hist<<<GS, T, 0, s>>>((const int2*)eidx, E);
    {
        size_t tb = 0;
        cub::DeviceScan::ExclusiveSum(nullptr, tb, (unsigned*)p_cnt, (unsigned*)p_off, n + 1, s);
        cub::DeviceScan::ExclusiveSum(p_temp, tb, (unsigned*)p_cnt, (unsigned*)p_off, n + 1, s);
    }
    k_bscatter<<<GS, T, 0, s>>>((const int2*)eidx, E);
    k_bsort<<<GS, T, 0, s>>>(n);
    {
        size_t tb = 0;
        cub::DeviceScan::ExclusiveSum(nullptr, tb, (unsigned*)p_ucnt, (unsigned*)p_uoff, n + 1, s);
        cub::DeviceScan::ExclusiveSum(p_temp, tb, (unsigned*)p_ucnt, (unsigned*)p_uoff, n + 1, s);
    }
    k_bemit<<<GS, T, 0, s>>>((float2*)(out + OFF_E), n);
    k_pad<<<GS, T, 0, s>>>((float2*)(out + OFF_E), E, n);
}